// round 15
// baseline (speedup 1.0000x reference)
#include <cuda_runtime.h>
#include <cuda_fp16.h>
#include <cstdint>

#define BATCH 64
#define SEQT  80
#define EMBD  100
#define KX    128
#define UN    2048
#define NCTA  128
#define NTHR  256
#define ABUF  8192
#define NBUF  3
#define SM_W  (NBUF*ABUF)              // weights at 24576
#define NSLOT 49
#define SM_TOTAL (SM_W + NSLOT*4096)   // 225280

__device__ __half g_h0[2][BATCH*UN];
__device__ __half g_h1[2][BATCH*UN];
__device__ __half g_X[SEQT*BATCH*KX];
__device__ __half g_Wh0[UN*UN];   // [n][k], fp16
__device__ __half g_Wx1[UN*UN];
__device__ __half g_Wh1[UN*UN];
__device__ __half g_Wx0[UN*KX];
__device__ float    g_part[64*4096];
__device__ unsigned g_flag[64];
__device__ unsigned g_sub[8*32];   // striped arrival counters, 128B apart
__device__ unsigned g_epoch;

extern __shared__ char smem[];

__device__ __forceinline__ uint32_t smem_u32(const void* p) {
    uint32_t a;
    asm("{ .reg .u64 t; cvta.to.shared.u64 t, %1; cvt.u32.u64 %0, t; }" : "=r"(a) : "l"(p));
    return a;
}
__device__ __forceinline__ void cpcg(uint32_t d, const void* s) {
    asm volatile("cp.async.cg.shared.global [%0], [%1], 16;" :: "r"(d), "l"(s));
}
#define CP_COMMIT() asm volatile("cp.async.commit_group;" ::: "memory")
#define CP_WAIT2()  asm volatile("cp.async.wait_group 2;" ::: "memory")
#define CP_WAIT1()  asm volatile("cp.async.wait_group 1;" ::: "memory")
#define CP_WAIT0()  asm volatile("cp.async.wait_group 0;" ::: "memory")

__device__ __forceinline__ void mma16816(float c[4], const uint32_t a[4], const uint32_t b[2]) {
    asm volatile("mma.sync.aligned.m16n8k16.row.col.f32.f16.f16.f32 "
        "{%0,%1,%2,%3}, {%4,%5,%6,%7}, {%8,%9}, {%0,%1,%2,%3};"
        : "+f"(c[0]), "+f"(c[1]), "+f"(c[2]), "+f"(c[3])
        : "r"(a[0]), "r"(a[1]), "r"(a[2]), "r"(a[3]), "r"(b[0]), "r"(b[1]));
}
__device__ __forceinline__ void ldm4(uint32_t r[4], uint32_t addr) {
    asm volatile("ldmatrix.sync.aligned.m8n8.x4.shared.b16 {%0,%1,%2,%3}, [%4];"
        : "=r"(r[0]), "=r"(r[1]), "=r"(r[2]), "=r"(r[3]) : "r"(addr));
}

// ---- prep kernels ----
__global__ void prep0(const int* __restrict__ inputs, const float* __restrict__ emb) {
    int idx = blockIdx.x * blockDim.x + threadIdx.x;
    int stride = gridDim.x * blockDim.x;
    __half z = __float2half(0.0f);
    for (int i = idx; i < BATCH * UN; i += stride) {
        g_h0[1][i] = z;
        g_h1[0][i] = z; g_h1[1][i] = z;
    }
    if (idx < 64) g_flag[idx] = 0u;
    if (idx < 256) g_sub[idx] = 0u;
    if (idx == 0) g_epoch = 0u;
    for (int i = idx; i < SEQT * BATCH * KX; i += stride) {
        int k = i & 127, b = (i >> 7) & 63, t = i >> 13;
        float v = (k < EMBD) ? emb[(size_t)inputs[b * SEQT + t] * EMBD + k] : 0.0f;
        g_X[i] = __float2half_rn(v);
    }
}
__global__ void wconv(const float* __restrict__ src, __half* __restrict__ dst,
                      int K, int N, int Kpad) {
    __shared__ float tile[32][33];
    int kb = blockIdx.y * 32, nb = blockIdx.x * 32;
    int tx = threadIdx.x, ty = threadIdx.y;
    #pragma unroll
    for (int j = 0; j < 32; j += 8) {
        int k = kb + ty + j;
        tile[ty + j][tx] = (k < K) ? src[(size_t)k * N + nb + tx] : 0.0f;
    }
    __syncthreads();
    #pragma unroll
    for (int j = 0; j < 32; j += 8) {
        int n = nb + ty + j, k = kb + tx;
        if (k < Kpad) dst[(size_t)n * Kpad + k] = __float2half_rn(tile[tx][ty + j]);
    }
}

// Hierarchical grid barrier: striped arrivals + CTA0 aggregation + epoch broadcast.
__device__ __forceinline__ void gbar(unsigned target) {
    __syncthreads();
    if (threadIdx.x == 0) {
        __threadfence();
        atomicAdd(&g_sub[(blockIdx.x & 7) << 5], 1u);
        if (blockIdx.x == 0) {
            unsigned s;
            do {
                s = 0;
                #pragma unroll
                for (int j = 0; j < 8; j++) {
                    unsigned v;
                    asm volatile("ld.acquire.gpu.u32 %0, [%1];"
                                 : "=r"(v) : "l"(&g_sub[j << 5]) : "memory");
                    s += v;
                }
            } while (s < target);
            asm volatile("st.release.gpu.u32 [%0], %1;"
                         :: "l"(&g_epoch), "r"(target) : "memory");
        } else {
            unsigned v;
            do {
                asm volatile("ld.acquire.gpu.u32 %0, [%1];"
                             : "=r"(v) : "l"(&g_epoch) : "memory");
            } while (v < target);
        }
    }
    __syncthreads();
}

// wslot -> A source for this phase.
// even: 0..14 Wh1-tail (A=h1prev kc=(17+s)*64); 15,16 X; 17..48 Wh0 (A=h0prev).
// odd:  0..31 Wx1 (A=h0prev); 32..48 Wh1 head (A=h1prev).
__device__ __forceinline__ const __half* asrc(bool even, int s, int p, int par0,
                                              int par1, int& astr) {
    astr = UN;
    if (even) {
        if (s < 15)  return g_h1[par1] + (17 + s) * 64;
        if (s < 17) { astr = KX; return g_X + (size_t)p * BATCH * KX + (s - 15) * 64; }
        return g_h0[par0] + (s - 17) * 64;
    }
    if (s < 32) return g_h0[par0] + s * 64;
    return g_h1[par1] + (s - 32) * 64;
}

__device__ __forceinline__ void stageA(const __half* a, int astr, uint32_t sb, int tid) {
    #pragma unroll
    for (int j = 0; j < 2; j++) {            // A: 64 rows x 8 x 16B
        int i = tid + NTHR * j;
        int r = i >> 3, q = i & 7;
        cpcg(sb + (uint32_t)(r * 128 + ((q ^ (r & 7)) << 4)),
             a + (size_t)r * astr + q * 8);
    }
}

// Warp (wk, wm, wn): M32 x N16 on its k32 half; single fp16 MMA per fragment.
__device__ __forceinline__ void gemm_chunk(uint32_t ab, uint32_t wb, int wk,
    const int offA[2], const int r7A[2], int offB, int r7B,
    int uAl, int uBl, float acc[2][2][4])
{
    #pragma unroll
    for (int kk = 0; kk < 2; kk++) {
        const int q0 = (wk * 2 + kk) * 2;
        uint32_t ah[2][4], bh[4];
        #pragma unroll
        for (int mt = 0; mt < 2; mt++)
            ldm4(ah[mt], ab + offA[mt] + (uint32_t)(((q0 + uAl) ^ r7A[mt]) << 4));
        ldm4(bh, wb + offB + (uint32_t)(((q0 + uBl) ^ r7B) << 4));
        #pragma unroll
        for (int mt = 0; mt < 2; mt++)
            #pragma unroll
            for (int nt = 0; nt < 2; nt++)
                mma16816(acc[mt][nt], ah[mt], bh + nt * 2);
    }
}

__global__ void __launch_bounds__(NTHR, 1) rnn_mma(
    const float* __restrict__ b0, const float* __restrict__ b1,
    const float* __restrict__ Wo, const float* __restrict__ bo,
    float* __restrict__ out)
{
    const int tid = threadIdx.x;
    const int wid = tid >> 5, lane = tid & 31;
    const int wk = wid >> 2;
    const int wsub = wid & 3, wm = wsub >> 1, wn = wsub & 1;
    const int gr = lane >> 2, gc = lane & 3;
    const int pair = blockIdx.x >> 1;
    const bool even = !(blockIdx.x & 1);
    const int cb = pair * 32;
    uint32_t su = smem_u32(smem);
    float* red = (float*)smem;               // overlaps dead A-buffers
    const float* bias = even ? b0 : b1;

    // ---- preload all 49 weight slabs into persistent smem ----
    {
        int r = tid >> 3, q = tid & 7;
        uint32_t doff = (uint32_t)(r * 128 + ((q ^ (r & 7)) << 4));
        for (int s = 0; s < NSLOT; s++) {
            const __half* w; int bstr = UN;
            if (even) {
                if (s < 15)       w = g_Wh1 + (size_t)cb * UN + (17 + s) * 64;
                else if (s < 17) { w = g_Wx0 + (size_t)cb * KX + (s - 15) * 64; bstr = KX; }
                else              w = g_Wh0 + (size_t)cb * UN + (s - 17) * 64;
            } else {
                if (s < 32) w = g_Wx1 + (size_t)cb * UN + s * 64;
                else        w = g_Wh1 + (size_t)cb * UN + (s - 32) * 64;
            }
            cpcg(su + SM_W + s * 4096 + doff, w + (size_t)r * bstr + q * 8);
        }
        CP_COMMIT();
        CP_WAIT0();
        __syncthreads();
    }

    int offA[2], r7A[2];
    #pragma unroll
    for (int mt = 0; mt < 2; mt++) {
        int row = wm * 32 + mt * 16 + (lane & 15);
        offA[mt] = row * 128;  r7A[mt] = row & 7;
    }
    const int nB = wn * 16 + (lane & 7) + ((lane >> 4) << 3);
    const int offB = nB * 128, r7B = nB & 7;
    const int uAl = lane >> 4;
    const int uBl = (lane >> 3) & 1;

    float bb[2][2];
    #pragma unroll
    for (int nt = 0; nt < 2; nt++) {
        int c = cb + wn * 16 + nt * 8 + 2 * gc;
        bb[nt][0] = bias[c]; bb[nt][1] = bias[c + 1];
    }

    for (int p = 0; p <= SEQT; p++) {
        const int par0 = (p + 1) & 1, par1 = p & 1;
        int gs, ge;
        if (even) { gs = (p < 2) ? 15 : 0;  ge = (p == 0) ? 17 : (p == SEQT ? 15 : 49); }
        else      { gs = 0;                 ge = (p == 0) ? 0 : 49; }
        float acc[2][2][4] = {};
        float* af = &acc[0][0][0];

        if (ge > gs) {
            int astr;
            // ---- prologue: stage 2 chunks ahead ----
            stageA(asrc(even, gs, p, par0, par1, astr), astr, su, tid);
            CP_COMMIT();
            if (ge - gs > 1) {
                const __half* a1 = asrc(even, gs + 1, p, par0, par1, astr);
                stageA(a1, astr, su + ABUF, tid);
                CP_COMMIT();
            }
            for (int g = gs; g < ge; g++) {
                if (g + 2 < ge) {
                    const __half* an = asrc(even, g + 2, p, par0, par1, astr);
                    stageA(an, astr, su + (uint32_t)(((g + 2 - gs) % NBUF) * ABUF), tid);
                    CP_COMMIT();
                    CP_WAIT2();
                } else if (g + 1 < ge) {
                    CP_WAIT1();
                } else {
                    CP_WAIT0();
                }
                __syncthreads();
                gemm_chunk(su + (uint32_t)(((g - gs) % NBUF) * ABUF),
                           su + SM_W + (uint32_t)(g * 4096), wk,
                           offA, r7A, offB, r7B, uAl, uBl, acc);

                if (even && g == 14) {
                    // ---- publish raw per-warp Wh1-tail partials ----
                    float* dst = g_part + (size_t)pair * 4096 + wid * 512 + lane * 16;
                    #pragma unroll
                    for (int i = 0; i < 16; i++) dst[i] = af[i];
                    __threadfence();
                    __syncthreads();
                    if (tid == 0)
                        asm volatile("st.release.gpu.u32 [%0], %1;"
                                     :: "l"(&g_flag[pair]), "r"((unsigned)p) : "memory");
                    #pragma unroll
                    for (int i = 0; i < 16; i++) af[i] = 0.0f;
                }
            }

            if (even) {
                if (p < SEQT) {
                    __syncthreads();
                    if (wk) {
                        int t = tid & 127;
                        #pragma unroll
                        for (int i = 0; i < 16; i++) red[i * 128 + t] = af[i];
                    }
                    __syncthreads();
                    if (!wk) {
                        #pragma unroll
                        for (int i = 0; i < 16; i++) af[i] += red[i * 128 + tid];
                        __half* dst = g_h0[p & 1];
                        #pragma unroll
                        for (int mt = 0; mt < 2; mt++)
                            #pragma unroll
                            for (int nt = 0; nt < 2; nt++)
                                #pragma unroll
                                for (int hrow = 0; hrow < 2; hrow++) {
                                    int r = wm * 32 + mt * 16 + gr + 8 * hrow;
                                    int c0 = cb + wn * 16 + nt * 8 + 2 * gc;
                                    float s0 = tanhf(acc[mt][nt][hrow * 2]     + bb[nt][0]);
                                    float s1 = tanhf(acc[mt][nt][hrow * 2 + 1] + bb[nt][1]);
                                    *(__half2*)(dst + (size_t)r * UN + c0) =
                                        __halves2half2(__float2half_rn(s0), __float2half_rn(s1));
                                }
                    }
                }
            } else {
                __syncthreads();
                if (wk) {
                    int t = tid & 127;
                    #pragma unroll
                    for (int i = 0; i < 16; i++) red[i * 128 + t] = af[i];
                }
                __syncthreads();
                if (p >= 2) {
                    if (tid == 0) {
                        unsigned v;
                        do {
                            asm volatile("ld.acquire.gpu.u32 %0, [%1];"
                                         : "=r"(v) : "l"(&g_flag[pair]) : "memory");
                        } while (v < (unsigned)p);
                    }
                    __syncthreads();
                }
                if (!wk) {
                    #pragma unroll
                    for (int i = 0; i < 16; i++) af[i] += red[i * 128 + tid];
                    if (p >= 2) {
                        const float* p0 = g_part + (size_t)pair * 4096 + wid * 512 + lane * 16;
                        const float* p1 = p0 + 4 * 512;
                        #pragma unroll
                        for (int i = 0; i < 16; i++) af[i] += p0[i] + p1[i];
                    }
                    __half* dst = g_h1[(p + 1) & 1];
                    #pragma unroll
                    for (int mt = 0; mt < 2; mt++)
                        #pragma unroll
                        for (int nt = 0; nt < 2; nt++)
                            #pragma unroll
                            for (int hrow = 0; hrow < 2; hrow++) {
                                int r = wm * 32 + mt * 16 + gr + 8 * hrow;
                                int c0 = cb + wn * 16 + nt * 8 + 2 * gc;
                                float s0 = tanhf(acc[mt][nt][hrow * 2]     + bb[nt][0]);
                                float s1 = tanhf(acc[mt][nt][hrow * 2 + 1] + bb[nt][1]);
                                *(__half2*)(dst + (size_t)r * UN + c0) =
                                    __halves2half2(__float2half_rn(s0), __float2half_rn(s1));
                            }
                }
            }
        }
        gbar((unsigned)(p + 1) * NCTA);
    }

    // ---- out[b] = sigmoid(h1_79 . Wo + bo); h1_79 in parity 1 ----
    if (blockIdx.x == 0) {
        const __half* hh = g_h1[1];
        const float bof = bo[0];
        for (int r = wid; r < BATCH; r += 8) {
            float s = 0.0f;
            for (int k = lane; k < UN; k += 32)
                s += __half2float(hh[(size_t)r * UN + k]) * Wo[k];
            #pragma unroll
            for (int o = 16; o > 0; o >>= 1)
                s += __shfl_xor_sync(0xffffffffu, s, o);
            if (lane == 0) out[r] = 1.0f / (1.0f + expf(-(s + bof)));
        }
    }
}

extern "C" void kernel_launch(void* const* d_in, const int* in_sizes, int n_in,
                              void* d_out, int out_size)
{
    const int*   inputs = (const int*)  d_in[0];
    const float* emb    = (const float*)d_in[1];
    const float* Wx0    = (const float*)d_in[2];
    const float* Wh0    = (const float*)d_in[3];
    const float* b0     = (const float*)d_in[4];
    const float* Wx1    = (const float*)d_in[5];
    const float* Wh1    = (const float*)d_in[6];
    const float* b1     = (const float*)d_in[7];
    const float* Wo     = (const float*)d_in[8];
    const float* bo     = (const float*)d_in[9];
    float* out = (float*)d_out;

    __half *wh0, *wx1, *wh1, *wx0;
    cudaGetSymbolAddress((void**)&wh0, g_Wh0);
    cudaGetSymbolAddress((void**)&wx1, g_Wx1);
    cudaGetSymbolAddress((void**)&wh1, g_Wh1);
    cudaGetSymbolAddress((void**)&wx0, g_Wx0);

    prep0<<<640, 256>>>(inputs, emb);
    dim3 tb(32, 8);
    wconv<<<dim3(UN/32, UN/32), tb>>>(Wh0, wh0, UN, UN, UN);
    wconv<<<dim3(UN/32, UN/32), tb>>>(Wx1, wx1, UN, UN, UN);
    wconv<<<dim3(UN/32, UN/32), tb>>>(Wh1, wh1, UN, UN, UN);
    wconv<<<dim3(UN/32, KX/32),  tb>>>(Wx0, wx0, EMBD, UN, KX);

    cudaFuncSetAttribute(rnn_mma, cudaFuncAttributeMaxDynamicSharedMemorySize, SM_TOTAL);
    rnn_mma<<<NCTA, NTHR, SM_TOTAL>>>(b0, b1, Wo, bo, out);
}

// round 16
// speedup vs baseline: 1.0827x; 1.0827x over previous
#include <cuda_runtime.h>
#include <cuda_fp16.h>
#include <cstdint>

#define BATCH 64
#define SEQT  80
#define EMBD  100
#define KX    128
#define UN    2048
#define NCTA  128
#define NTHR  256
#define ABUF  8192
#define NBUF  3
#define SM_W  (NBUF*ABUF)
#define NSLOT 49
#define SM_TOTAL (SM_W + NSLOT*4096)   // 225280
#define PARTSZ (64*4096)

__device__ __half g_h0[3][BATCH*UN];
__device__ __half g_h1[3][BATCH*UN];
__device__ __half g_X[SEQT*BATCH*KX];
__device__ __half g_Wh0[UN*UN];
__device__ __half g_Wx1[UN*UN];
__device__ __half g_Wh1[UN*UN];
__device__ __half g_Wx0[UN*KX];
__device__ float    g_part[2*PARTSZ];
__device__ unsigned g_flag[64];
__device__ unsigned g_cnt[96];     // [0]=c_h0, [32]=c_h1, [64]=c_done

extern __shared__ char smem[];

__device__ __forceinline__ uint32_t smem_u32(const void* p) {
    uint32_t a;
    asm("{ .reg .u64 t; cvta.to.shared.u64 t, %1; cvt.u32.u64 %0, t; }" : "=r"(a) : "l"(p));
    return a;
}
__device__ __forceinline__ void cpcg(uint32_t d, const void* s) {
    asm volatile("cp.async.cg.shared.global [%0], [%1], 16;" :: "r"(d), "l"(s));
}
#define CP_COMMIT() asm volatile("cp.async.commit_group;" ::: "memory")
#define CP_WAIT2()  asm volatile("cp.async.wait_group 2;" ::: "memory")
#define CP_WAIT1()  asm volatile("cp.async.wait_group 1;" ::: "memory")
#define CP_WAIT0()  asm volatile("cp.async.wait_group 0;" ::: "memory")

// tid0 spins until *addr >= tgt, then CTA proceeds.
#define SPIN_GE(addr, tgt) do {                                              \
    if (tid == 0) {                                                          \
        unsigned _v;                                                         \
        do {                                                                 \
            asm volatile("ld.acquire.gpu.u32 %0, [%1];"                      \
                         : "=r"(_v) : "l"(addr) : "memory");                 \
        } while (_v < (unsigned)(tgt));                                      \
    }                                                                        \
    __syncthreads();                                                         \
} while (0)

__device__ __forceinline__ void mma16816(float c[4], const uint32_t a[4], const uint32_t b[2]) {
    asm volatile("mma.sync.aligned.m16n8k16.row.col.f32.f16.f16.f32 "
        "{%0,%1,%2,%3}, {%4,%5,%6,%7}, {%8,%9}, {%0,%1,%2,%3};"
        : "+f"(c[0]), "+f"(c[1]), "+f"(c[2]), "+f"(c[3])
        : "r"(a[0]), "r"(a[1]), "r"(a[2]), "r"(a[3]), "r"(b[0]), "r"(b[1]));
}
__device__ __forceinline__ void ldm4(uint32_t r[4], uint32_t addr) {
    asm volatile("ldmatrix.sync.aligned.m8n8.x4.shared.b16 {%0,%1,%2,%3}, [%4];"
        : "=r"(r[0]), "=r"(r[1]), "=r"(r[2]), "=r"(r[3]) : "r"(addr));
}

// ---- prep kernels ----
__global__ void prep0(const int* __restrict__ inputs, const float* __restrict__ emb) {
    int idx = blockIdx.x * blockDim.x + threadIdx.x;
    int stride = gridDim.x * blockDim.x;
    __half z = __float2half(0.0f);
    for (int i = idx; i < BATCH * UN; i += stride)
        g_h1[2][i] = z;                       // h1_{-1}
    if (idx < 64) g_flag[idx] = 0u;
    if (idx < 96) g_cnt[idx] = 0u;
    for (int i = idx; i < SEQT * BATCH * KX; i += stride) {
        int k = i & 127, b = (i >> 7) & 63, t = i >> 13;
        float v = (k < EMBD) ? emb[(size_t)inputs[b * SEQT + t] * EMBD + k] : 0.0f;
        g_X[i] = __float2half_rn(v);
    }
}
__global__ void wconv(const float* __restrict__ src, __half* __restrict__ dst,
                      int K, int N, int Kpad) {
    __shared__ float tile[32][33];
    int kb = blockIdx.y * 32, nb = blockIdx.x * 32;
    int tx = threadIdx.x, ty = threadIdx.y;
    #pragma unroll
    for (int j = 0; j < 32; j += 8) {
        int k = kb + ty + j;
        tile[ty + j][tx] = (k < K) ? src[(size_t)k * N + nb + tx] : 0.0f;
    }
    __syncthreads();
    #pragma unroll
    for (int j = 0; j < 32; j += 8) {
        int n = nb + ty + j, k = kb + tx;
        if (k < Kpad) dst[(size_t)n * Kpad + k] = __float2half_rn(tile[tx][ty + j]);
    }
}

// wslot -> A source for this phase (3-deep buffers).
__device__ __forceinline__ const __half* asrc(bool even, int s, int p, int rd0,
                                              int rd1, int& astr) {
    astr = UN;
    if (even) {
        if (s < 15)  return g_h1[rd1] + (17 + s) * 64;
        if (s < 17) { astr = KX; return g_X + (size_t)p * BATCH * KX + (s - 15) * 64; }
        return g_h0[rd0] + (s - 17) * 64;
    }
    if (s < 32) return g_h0[rd0] + s * 64;
    return g_h1[rd1] + (s - 32) * 64;
}

__device__ __forceinline__ void stageA(const __half* a, int astr, uint32_t sb, int tid) {
    #pragma unroll
    for (int j = 0; j < 2; j++) {
        int i = tid + NTHR * j;
        int r = i >> 3, q = i & 7;
        cpcg(sb + (uint32_t)(r * 128 + ((q ^ (r & 7)) << 4)),
             a + (size_t)r * astr + q * 8);
    }
}

__device__ __forceinline__ void gemm_chunk(uint32_t ab, uint32_t wb, int wk,
    const int offA[2], const int r7A[2], int offB, int r7B,
    int uAl, int uBl, float acc[2][2][4])
{
    #pragma unroll
    for (int kk = 0; kk < 2; kk++) {
        const int q0 = (wk * 2 + kk) * 2;
        uint32_t ah[2][4], bh[4];
        #pragma unroll
        for (int mt = 0; mt < 2; mt++)
            ldm4(ah[mt], ab + offA[mt] + (uint32_t)(((q0 + uAl) ^ r7A[mt]) << 4));
        ldm4(bh, wb + offB + (uint32_t)(((q0 + uBl) ^ r7B) << 4));
        #pragma unroll
        for (int mt = 0; mt < 2; mt++)
            #pragma unroll
            for (int nt = 0; nt < 2; nt++)
                mma16816(acc[mt][nt], ah[mt], bh + nt * 2);
    }
}

__global__ void __launch_bounds__(NTHR, 1) rnn_mma(
    const float* __restrict__ b0, const float* __restrict__ b1,
    const float* __restrict__ Wo, const float* __restrict__ bo,
    float* __restrict__ out)
{
    const int tid = threadIdx.x;
    const int wid = tid >> 5, lane = tid & 31;
    const int wk = wid >> 2;
    const int wsub = wid & 3, wm = wsub >> 1, wn = wsub & 1;
    const int gr = lane >> 2, gc = lane & 3;
    const int pair = blockIdx.x >> 1;
    const bool even = !(blockIdx.x & 1);
    const int cb = pair * 32;
    uint32_t su = smem_u32(smem);
    float* red = (float*)smem;
    const float* bias = even ? b0 : b1;
    unsigned* c_h0 = &g_cnt[0];
    unsigned* c_h1 = &g_cnt[32];
    unsigned* c_done = &g_cnt[64];

    // ---- preload weight slabs ----
    {
        int r = tid >> 3, q = tid & 7;
        uint32_t doff = (uint32_t)(r * 128 + ((q ^ (r & 7)) << 4));
        for (int s = 0; s < NSLOT; s++) {
            const __half* w; int bstr = UN;
            if (even) {
                if (s < 15)       w = g_Wh1 + (size_t)cb * UN + (17 + s) * 64;
                else if (s < 17) { w = g_Wx0 + (size_t)cb * KX + (s - 15) * 64; bstr = KX; }
                else              w = g_Wh0 + (size_t)cb * UN + (s - 17) * 64;
            } else {
                if (s < 32) w = g_Wx1 + (size_t)cb * UN + s * 64;
                else        w = g_Wh1 + (size_t)cb * UN + (s - 32) * 64;
            }
            cpcg(su + SM_W + s * 4096 + doff, w + (size_t)r * bstr + q * 8);
        }
        CP_COMMIT();
        CP_WAIT0();
        __syncthreads();
    }

    int offA[2], r7A[2];
    #pragma unroll
    for (int mt = 0; mt < 2; mt++) {
        int row = wm * 32 + mt * 16 + (lane & 15);
        offA[mt] = row * 128;  r7A[mt] = row & 7;
    }
    const int nB = wn * 16 + (lane & 7) + ((lane >> 4) << 3);
    const int offB = nB * 128, r7B = nB & 7;
    const int uAl = lane >> 4;
    const int uBl = (lane >> 3) & 1;

    float bb[2][2];
    #pragma unroll
    for (int nt = 0; nt < 2; nt++) {
        int c = cb + wn * 16 + nt * 8 + 2 * gc;
        bb[nt][0] = bias[c]; bb[nt][1] = bias[c + 1];
    }

    for (int p = 0; p <= SEQT; p++) {
        const int rd0 = (p + 2) % 3;         // h0_{p-1}
        const int rd1 = (p + 1) % 3;         // h1_{p-2}
        const int wr0 = p % 3;               // h0_p
        const int wr1 = (p + 2) % 3;         // h1_{p-1}
        int gs, ge;
        if (even) { gs = (p < 2) ? 15 : 0;  ge = (p == 0) ? 17 : (p == SEQT ? 15 : 49); }
        else      { gs = 0;                 ge = (p == 0) ? 0 : 49; }
        float acc[2][2][4] = {};
        float* af = &acc[0][0][0];

        // write guard: all CTAs finished phase p-2 (2-phase slack)
        if (p >= 2) SPIN_GE(c_done, 128u * (unsigned)(p - 1));

        if (ge > gs) {
            // read guards for prologue sources
            if (even) {
                if (p >= 2) SPIN_GE(c_h1, 64u * (unsigned)(p - 1));   // tail: h1_{p-2}
            } else {
                SPIN_GE(c_h0, 64u * (unsigned)p);                     // slot0: h0_{p-1}
            }
            int astr;
            stageA(asrc(even, gs, p, rd0, rd1, astr), astr, su, tid);
            CP_COMMIT();
            if (ge - gs > 1) {
                const __half* a1 = asrc(even, gs + 1, p, rd0, rd1, astr);
                stageA(a1, astr, su + ABUF, tid);
                CP_COMMIT();
            }
            for (int g = gs; g < ge; g++) {
                if (g + 2 < ge) {
                    // late read guards
                    if (even && g + 2 == 17) SPIN_GE(c_h0, 64u * (unsigned)p);
                    if (!even && g + 2 == 32 && p >= 2)
                        SPIN_GE(c_h1, 64u * (unsigned)(p - 1));
                    const __half* an = asrc(even, g + 2, p, rd0, rd1, astr);
                    stageA(an, astr, su + (uint32_t)(((g + 2 - gs) % NBUF) * ABUF), tid);
                    CP_COMMIT();
                    CP_WAIT2();
                } else if (g + 1 < ge) {
                    CP_WAIT1();
                } else {
                    CP_WAIT0();
                }
                __syncthreads();
                gemm_chunk(su + (uint32_t)(((g - gs) % NBUF) * ABUF),
                           su + SM_W + (uint32_t)(g * 4096), wk,
                           offA, r7A, offB, r7B, uAl, uBl, acc);

                if (even && g == 14) {
                    float* dst = g_part + (size_t)(p & 1) * PARTSZ
                               + (size_t)pair * 4096 + wid * 512 + lane * 16;
                    #pragma unroll
                    for (int i = 0; i < 16; i++) dst[i] = af[i];
                    __threadfence();
                    __syncthreads();
                    if (tid == 0)
                        asm volatile("st.release.gpu.u32 [%0], %1;"
                                     :: "l"(&g_flag[pair]), "r"((unsigned)p) : "memory");
                    #pragma unroll
                    for (int i = 0; i < 16; i++) af[i] = 0.0f;
                }
            }

            if (even) {
                if (p < SEQT) {
                    __syncthreads();
                    if (wk) {
                        int t = tid & 127;
                        #pragma unroll
                        for (int i = 0; i < 16; i++) red[i * 128 + t] = af[i];
                    }
                    __syncthreads();
                    if (!wk) {
                        #pragma unroll
                        for (int i = 0; i < 16; i++) af[i] += red[i * 128 + tid];
                        __half* dst = g_h0[wr0];
                        #pragma unroll
                        for (int mt = 0; mt < 2; mt++)
                            #pragma unroll
                            for (int nt = 0; nt < 2; nt++)
                                #pragma unroll
                                for (int hrow = 0; hrow < 2; hrow++) {
                                    int r = wm * 32 + mt * 16 + gr + 8 * hrow;
                                    int c0 = cb + wn * 16 + nt * 8 + 2 * gc;
                                    float s0 = tanhf(acc[mt][nt][hrow * 2]     + bb[nt][0]);
                                    float s1 = tanhf(acc[mt][nt][hrow * 2 + 1] + bb[nt][1]);
                                    *(__half2*)(dst + (size_t)r * UN + c0) =
                                        __halves2half2(__float2half_rn(s0), __float2half_rn(s1));
                                }
                        __threadfence();
                    }
                    __syncthreads();
                    if (tid == 0) atomicAdd(c_h0, 1u);
                }
            } else {
                __syncthreads();
                if (wk) {
                    int t = tid & 127;
                    #pragma unroll
                    for (int i = 0; i < 16; i++) red[i * 128 + t] = af[i];
                }
                __syncthreads();
                if (p >= 2) {
                    if (tid == 0) {
                        unsigned v;
                        do {
                            asm volatile("ld.acquire.gpu.u32 %0, [%1];"
                                         : "=r"(v) : "l"(&g_flag[pair]) : "memory");
                        } while (v < (unsigned)p);
                    }
                    __syncthreads();
                }
                if (!wk) {
                    #pragma unroll
                    for (int i = 0; i < 16; i++) af[i] += red[i * 128 + tid];
                    if (p >= 2) {
                        const float* p0 = g_part + (size_t)(p & 1) * PARTSZ
                                        + (size_t)pair * 4096 + wid * 512 + lane * 16;
                        const float* p1 = p0 + 4 * 512;
                        #pragma unroll
                        for (int i = 0; i < 16; i++) af[i] += p0[i] + p1[i];
                    }
                    __half* dst = g_h1[wr1];
                    #pragma unroll
                    for (int mt = 0; mt < 2; mt++)
                        #pragma unroll
                        for (int nt = 0; nt < 2; nt++)
                            #pragma unroll
                            for (int hrow = 0; hrow < 2; hrow++) {
                                int r = wm * 32 + mt * 16 + gr + 8 * hrow;
                                int c0 = cb + wn * 16 + nt * 8 + 2 * gc;
                                float s0 = tanhf(acc[mt][nt][hrow * 2]     + bb[nt][0]);
                                float s1 = tanhf(acc[mt][nt][hrow * 2 + 1] + bb[nt][1]);
                                *(__half2*)(dst + (size_t)r * UN + c0) =
                                    __halves2half2(__float2half_rn(s0), __float2half_rn(s1));
                            }
                    __threadfence();
                }
                __syncthreads();
                if (tid == 0) atomicAdd(c_h1, 1u);
            }
        }
        // phase-completion signal (all CTAs, every phase)
        __syncthreads();
        if (tid == 0) atomicAdd(c_done, 1u);
    }

    // ---- out[b] = sigmoid(h1_79 . Wo + bo); h1_79 in buf (80+2)%3 = 1 ----
    if (blockIdx.x == 0) {
        SPIN_GE(&g_cnt[32], 64u * (unsigned)SEQT);
        const __half* hh = g_h1[(SEQT + 2) % 3];
        const float bof = bo[0];
        for (int r = wid; r < BATCH; r += 8) {
            float s = 0.0f;
            for (int k = lane; k < UN; k += 32)
                s += __half2float(hh[(size_t)r * UN + k]) * Wo[k];
            #pragma unroll
            for (int o = 16; o > 0; o >>= 1)
                s += __shfl_xor_sync(0xffffffffu, s, o);
            if (lane == 0) out[r] = 1.0f / (1.0f + expf(-(s + bof)));
        }
    }
}

extern "C" void kernel_launch(void* const* d_in, const int* in_sizes, int n_in,
                              void* d_out, int out_size)
{
    const int*   inputs = (const int*)  d_in[0];
    const float* emb    = (const float*)d_in[1];
    const float* Wx0    = (const float*)d_in[2];
    const float* Wh0    = (const float*)d_in[3];
    const float* b0     = (const float*)d_in[4];
    const float* Wx1    = (const float*)d_in[5];
    const float* Wh1    = (const float*)d_in[6];
    const float* b1     = (const float*)d_in[7];
    const float* Wo     = (const float*)d_in[8];
    const float* bo     = (const float*)d_in[9];
    float* out = (float*)d_out;

    __half *wh0, *wx1, *wh1, *wx0;
    cudaGetSymbolAddress((void**)&wh0, g_Wh0);
    cudaGetSymbolAddress((void**)&wx1, g_Wx1);
    cudaGetSymbolAddress((void**)&wh1, g_Wh1);
    cudaGetSymbolAddress((void**)&wx0, g_Wx0);

    prep0<<<640, 256>>>(inputs, emb);
    dim3 tb(32, 8);
    wconv<<<dim3(UN/32, UN/32), tb>>>(Wh0, wh0, UN, UN, UN);
    wconv<<<dim3(UN/32, UN/32), tb>>>(Wx1, wx1, UN, UN, UN);
    wconv<<<dim3(UN/32, UN/32), tb>>>(Wh1, wh1, UN, UN, UN);
    wconv<<<dim3(UN/32, KX/32),  tb>>>(Wx0, wx0, EMBD, UN, KX);

    cudaFuncSetAttribute(rnn_mma, cudaFuncAttributeMaxDynamicSharedMemorySize, SM_TOTAL);
    rnn_mma<<<NCTA, NTHR, SM_TOTAL>>>(b0, b1, Wo, bo, out);
}

// round 17
// speedup vs baseline: 1.5094x; 1.3941x over previous
#include <cuda_runtime.h>
#include <cuda_fp16.h>
#include <cstdint>

#define BATCH 64
#define SEQT  80
#define EMBD  100
#define KP    256              // padded K for the X GEMM
#define UN    2048
#define NCTA  128
#define NTHR  256
#define STGB  49152             // A 32KB | W 16KB
#define NBUF  3
#define SM_TOTAL (NBUF*STGB)    // 147456

__device__ __half g_h0[2][BATCH*UN];
__device__ __half g_h1[2][BATCH*UN];
__device__ __half g_X[SEQT*BATCH*KP];     // zero-padded k100->256
__device__ __half g_Wh0[UN*UN];           // [n][k]
__device__ __half g_Wx1[UN*UN];
__device__ __half g_Wh1[UN*UN];
__device__ __half g_Wx0[UN*KP];           // [n][256], zero-padded
__device__ float    g_part[64*4096];
__device__ unsigned g_flag[64];
__device__ unsigned g_gbar;

extern __shared__ char smem[];

__device__ __forceinline__ uint32_t smem_u32(const void* p) {
    uint32_t a;
    asm("{ .reg .u64 t; cvta.to.shared.u64 t, %1; cvt.u32.u64 %0, t; }" : "=r"(a) : "l"(p));
    return a;
}
__device__ __forceinline__ void cpcg(uint32_t d, const void* s) {
    asm volatile("cp.async.cg.shared.global [%0], [%1], 16;" :: "r"(d), "l"(s));
}
#define CP_COMMIT() asm volatile("cp.async.commit_group;" ::: "memory")
#define CP_WAIT2()  asm volatile("cp.async.wait_group 2;" ::: "memory")
#define CP_WAIT1()  asm volatile("cp.async.wait_group 1;" ::: "memory")
#define CP_WAIT0()  asm volatile("cp.async.wait_group 0;" ::: "memory")

__device__ __forceinline__ void mma16816(float c[4], const uint32_t a[4], const uint32_t b[2]) {
    asm volatile("mma.sync.aligned.m16n8k16.row.col.f32.f16.f16.f32 "
        "{%0,%1,%2,%3}, {%4,%5,%6,%7}, {%8,%9}, {%0,%1,%2,%3};"
        : "+f"(c[0]), "+f"(c[1]), "+f"(c[2]), "+f"(c[3])
        : "r"(a[0]), "r"(a[1]), "r"(a[2]), "r"(a[3]), "r"(b[0]), "r"(b[1]));
}
__device__ __forceinline__ void ldm4(uint32_t r[4], uint32_t addr) {
    asm volatile("ldmatrix.sync.aligned.m8n8.x4.shared.b16 {%0,%1,%2,%3}, [%4];"
        : "=r"(r[0]), "=r"(r[1]), "=r"(r[2]), "=r"(r[3]) : "r"(addr));
}

// ---- prep kernels ----
__global__ void prep0(const int* __restrict__ inputs, const float* __restrict__ emb) {
    int idx = blockIdx.x * blockDim.x + threadIdx.x;
    int stride = gridDim.x * blockDim.x;
    __half z = __float2half(0.0f);
    for (int i = idx; i < BATCH * UN; i += stride) {
        g_h0[1][i] = z;
        g_h1[0][i] = z; g_h1[1][i] = z;
    }
    if (idx < 64) g_flag[idx] = 0u;
    if (idx == 0) g_gbar = 0u;
    for (int i = idx; i < SEQT * BATCH * KP; i += stride) {
        int k = i & 255, b = (i >> 8) & 63, t = i >> 14;
        float v = (k < EMBD) ? emb[(size_t)inputs[b * SEQT + t] * EMBD + k] : 0.0f;
        g_X[i] = __float2half_rn(v);
    }
}
__global__ void wconv(const float* __restrict__ src, __half* __restrict__ dst,
                      int K, int N, int Kpad) {
    __shared__ float tile[32][33];
    int kb = blockIdx.y * 32, nb = blockIdx.x * 32;
    int tx = threadIdx.x, ty = threadIdx.y;
    #pragma unroll
    for (int j = 0; j < 32; j += 8) {
        int k = kb + ty + j;
        tile[ty + j][tx] = (k < K) ? src[(size_t)k * N + nb + tx] : 0.0f;
    }
    __syncthreads();
    #pragma unroll
    for (int j = 0; j < 32; j += 8) {
        int n = nb + ty + j, k = kb + tx;
        if (k < Kpad) dst[(size_t)n * Kpad + k] = __float2half_rn(tile[tx][ty + j]);
    }
}

__device__ __forceinline__ void gbar(unsigned target) {
    __syncthreads();
    if (threadIdx.x == 0) {
        __threadfence();
        atomicAdd(&g_gbar, 1u);
        unsigned v;
        do {
            asm volatile("ld.acquire.gpu.u32 %0, [%1];" : "=r"(v) : "l"(&g_gbar) : "memory");
        } while (v < target);
    }
    __syncthreads();
}

struct Ck { const __half *a, *w; int astr, wstr; };

// even: 0..3 Wh1-tail (kc 1024+g*256); 4 = X (padded k256); 5..12 Wh0.
// odd:  0..7 Wx1; 8..11 Wh1 head (kc 0..1023).
__device__ __forceinline__ Ck dec(bool even, int g, int p, int par0, int par1, int cb) {
    Ck c; c.astr = UN; c.wstr = UN;
    if (even) {
        if (g < 4) {
            int kc = 1024 + g * 256;
            c.a = g_h1[par1] + kc;
            c.w = g_Wh1 + (size_t)cb * UN + kc;
        } else if (g == 4) {
            c.a = g_X + (size_t)p * BATCH * KP;  c.astr = KP;
            c.w = g_Wx0 + (size_t)cb * KP;       c.wstr = KP;
        } else {
            int kc = (g - 5) * 256;
            c.a = g_h0[par0] + kc;
            c.w = g_Wh0 + (size_t)cb * UN + kc;
        }
    } else {
        if (g < 8) {
            int kc = g * 256;
            c.a = g_h0[par0] + kc;
            c.w = g_Wx1 + (size_t)cb * UN + kc;
        } else {
            int kc = (g - 8) * 256;
            c.a = g_h1[par1] + kc;
            c.w = g_Wh1 + (size_t)cb * UN + kc;
        }
    }
    return c;
}

// Stage one k256 chunk: A 64x256 fp16 (32KB), W 32x256 fp16 (16KB).
__device__ __forceinline__ void stage(const Ck& c, uint32_t sb, int tid) {
    #pragma unroll
    for (int j = 0; j < 8; j++) {
        int i = tid + NTHR * j;
        int r = i >> 5, q = i & 31;
        cpcg(sb + (uint32_t)(r * 512 + ((q ^ (r & 7)) << 4)),
             c.a + (size_t)r * c.astr + q * 8);
    }
    #pragma unroll
    for (int j = 0; j < 4; j++) {
        int i = tid + NTHR * j;
        int r = i >> 5, q = i & 31;
        cpcg(sb + 32768 + (uint32_t)(r * 512 + ((q ^ (r & 7)) << 4)),
             c.w + (size_t)r * c.wstr + q * 8);
    }
}

// Warp (wk, wm, wn): M32 x N16 on its k128 half of the k256 chunk.
__device__ __forceinline__ void gemm_chunk(uint32_t sb, int wk,
    const int offA[2], const int r7A[2], int offB, int r7B,
    int uAl, int uBl, float acc[2][2][4])
{
    #pragma unroll
    for (int kk = 0; kk < 8; kk++) {
        const int q0 = wk * 16 + kk * 2;
        uint32_t ah[2][4], bh[4];
        #pragma unroll
        for (int mt = 0; mt < 2; mt++)
            ldm4(ah[mt], sb + offA[mt] + (uint32_t)(((q0 + uAl) ^ r7A[mt]) << 4));
        ldm4(bh, sb + 32768 + offB + (uint32_t)(((q0 + uBl) ^ r7B) << 4));
        #pragma unroll
        for (int mt = 0; mt < 2; mt++)
            #pragma unroll
            for (int nt = 0; nt < 2; nt++)
                mma16816(acc[mt][nt], ah[mt], bh + nt * 2);
    }
}

__global__ void __launch_bounds__(NTHR, 1) rnn_mma(
    const float* __restrict__ b0, const float* __restrict__ b1,
    const float* __restrict__ Wo, const float* __restrict__ bo,
    float* __restrict__ out)
{
    const int tid = threadIdx.x;
    const int wid = tid >> 5, lane = tid & 31;
    const int wk = wid >> 2;
    const int wsub = wid & 3, wm = wsub >> 1, wn = wsub & 1;
    const int gr = lane >> 2, gc = lane & 3;
    const int pair = blockIdx.x >> 1;
    const bool even = !(blockIdx.x & 1);
    const int cb = pair * 32;
    uint32_t su = smem_u32(smem);
    float* red = (float*)smem;               // overlaps buf0 (sync'd)
    const float* bias = even ? b0 : b1;

    int offA[2], r7A[2];
    #pragma unroll
    for (int mt = 0; mt < 2; mt++) {
        int row = wm * 32 + mt * 16 + (lane & 15);
        offA[mt] = row * 512;  r7A[mt] = row & 7;
    }
    const int nB = wn * 16 + (lane & 7) + ((lane >> 4) << 3);
    const int offB = nB * 512, r7B = nB & 7;
    const int uAl = lane >> 4;
    const int uBl = (lane >> 3) & 1;

    float bb[2][2];
    #pragma unroll
    for (int nt = 0; nt < 2; nt++) {
        int c = cb + wn * 16 + nt * 8 + 2 * gc;
        bb[nt][0] = bias[c]; bb[nt][1] = bias[c + 1];
    }

    for (int p = 0; p <= SEQT; p++) {
        const int par0 = (p + 1) & 1, par1 = p & 1;
        int gs, ge;
        if (even) { gs = (p < 2) ? 4 : 0;  ge = (p == 0) ? 5 : (p == SEQT ? 4 : 13); }
        else      { gs = 0;                ge = (p == 0) ? 0 : 12; }
        float acc[2][2][4] = {};
        float* af = &acc[0][0][0];

        if (ge > gs) {
            // ---- prologue: 2 chunks ahead ----
            stage(dec(even, gs, p, par0, par1, cb), su, tid);
            CP_COMMIT();
            if (ge - gs > 1) {
                stage(dec(even, gs + 1, p, par0, par1, cb), su + STGB, tid);
                CP_COMMIT();
            }
            for (int g = gs; g < ge; g++) {
                if (g + 2 < ge) {
                    stage(dec(even, g + 2, p, par0, par1, cb),
                          su + (uint32_t)(((g + 2 - gs) % NBUF) * STGB), tid);
                    CP_COMMIT();
                    CP_WAIT2();
                } else if (g + 1 < ge) {
                    CP_WAIT1();
                } else {
                    CP_WAIT0();
                }
                __syncthreads();
                gemm_chunk(su + (uint32_t)(((g - gs) % NBUF) * STGB), wk,
                           offA, r7A, offB, r7B, uAl, uBl, acc);

                if (even && p >= 2 && g == 3) {
                    // ---- publish raw per-warp Wh1-tail partials ----
                    float* dst = g_part + (size_t)pair * 4096 + wid * 512 + lane * 16;
                    #pragma unroll
                    for (int i = 0; i < 16; i++) dst[i] = af[i];
                    __threadfence();
                    __syncthreads();
                    if (tid == 0)
                        asm volatile("st.release.gpu.u32 [%0], %1;"
                                     :: "l"(&g_flag[pair]), "r"((unsigned)p) : "memory");
                    #pragma unroll
                    for (int i = 0; i < 16; i++) af[i] = 0.0f;
                }
            }

            if (even) {
                if (p < SEQT) {
                    __syncthreads();
                    if (wk) {
                        int t = tid & 127;
                        #pragma unroll
                        for (int i = 0; i < 16; i++) red[i * 128 + t] = af[i];
                    }
                    __syncthreads();
                    if (!wk) {
                        #pragma unroll
                        for (int i = 0; i < 16; i++) af[i] += red[i * 128 + tid];
                        __half* dst = g_h0[p & 1];
                        #pragma unroll
                        for (int mt = 0; mt < 2; mt++)
                            #pragma unroll
                            for (int nt = 0; nt < 2; nt++)
                                #pragma unroll
                                for (int hrow = 0; hrow < 2; hrow++) {
                                    int r = wm * 32 + mt * 16 + gr + 8 * hrow;
                                    int c0 = cb + wn * 16 + nt * 8 + 2 * gc;
                                    float s0 = tanhf(acc[mt][nt][hrow * 2]     + bb[nt][0]);
                                    float s1 = tanhf(acc[mt][nt][hrow * 2 + 1] + bb[nt][1]);
                                    *(__half2*)(dst + (size_t)r * UN + c0) =
                                        __halves2half2(__float2half_rn(s0), __float2half_rn(s1));
                                }
                    }
                }
            } else {
                __syncthreads();
                if (wk) {
                    int t = tid & 127;
                    #pragma unroll
                    for (int i = 0; i < 16; i++) red[i * 128 + t] = af[i];
                }
                __syncthreads();
                if (p >= 2) {
                    if (tid == 0) {
                        unsigned v;
                        do {
                            asm volatile("ld.acquire.gpu.u32 %0, [%1];"
                                         : "=r"(v) : "l"(&g_flag[pair]) : "memory");
                        } while (v < (unsigned)p);
                    }
                    __syncthreads();
                }
                if (!wk) {
                    #pragma unroll
                    for (int i = 0; i < 16; i++) af[i] += red[i * 128 + tid];
                    if (p >= 2) {
                        const float* p0 = g_part + (size_t)pair * 4096 + wid * 512 + lane * 16;
                        const float* p1 = p0 + 4 * 512;
                        #pragma unroll
                        for (int i = 0; i < 16; i++) af[i] += p0[i] + p1[i];
                    }
                    __half* dst = g_h1[(p + 1) & 1];
                    #pragma unroll
                    for (int mt = 0; mt < 2; mt++)
                        #pragma unroll
                        for (int nt = 0; nt < 2; nt++)
                            #pragma unroll
                            for (int hrow = 0; hrow < 2; hrow++) {
                                int r = wm * 32 + mt * 16 + gr + 8 * hrow;
                                int c0 = cb + wn * 16 + nt * 8 + 2 * gc;
                                float s0 = tanhf(acc[mt][nt][hrow * 2]     + bb[nt][0]);
                                float s1 = tanhf(acc[mt][nt][hrow * 2 + 1] + bb[nt][1]);
                                *(__half2*)(dst + (size_t)r * UN + c0) =
                                    __halves2half2(__float2half_rn(s0), __float2half_rn(s1));
                            }
                }
            }
        }
        gbar((unsigned)(p + 1) * NCTA);
    }

    // ---- out[b] = sigmoid(h1_79 . Wo + bo); h1_79 in parity 1 ----
    if (blockIdx.x == 0) {
        const __half* hh = g_h1[1];
        const float bof = bo[0];
        for (int r = wid; r < BATCH; r += 8) {
            float s = 0.0f;
            for (int k = lane; k < UN; k += 32)
                s += __half2float(hh[(size_t)r * UN + k]) * Wo[k];
            #pragma unroll
            for (int o = 16; o > 0; o >>= 1)
                s += __shfl_xor_sync(0xffffffffu, s, o);
            if (lane == 0) out[r] = 1.0f / (1.0f + expf(-(s + bof)));
        }
    }
}

extern "C" void kernel_launch(void* const* d_in, const int* in_sizes, int n_in,
                              void* d_out, int out_size)
{
    const int*   inputs = (const int*)  d_in[0];
    const float* emb    = (const float*)d_in[1];
    const float* Wx0    = (const float*)d_in[2];
    const float* Wh0    = (const float*)d_in[3];
    const float* b0     = (const float*)d_in[4];
    const float* Wx1    = (const float*)d_in[5];
    const float* Wh1    = (const float*)d_in[6];
    const float* b1     = (const float*)d_in[7];
    const float* Wo     = (const float*)d_in[8];
    const float* bo     = (const float*)d_in[9];
    float* out = (float*)d_out;

    __half *wh0, *wx1, *wh1, *wx0;
    cudaGetSymbolAddress((void**)&wh0, g_Wh0);
    cudaGetSymbolAddress((void**)&wx1, g_Wx1);
    cudaGetSymbolAddress((void**)&wh1, g_Wh1);
    cudaGetSymbolAddress((void**)&wx0, g_Wx0);

    prep0<<<640, 256>>>(inputs, emb);
    dim3 tb(32, 8);
    wconv<<<dim3(UN/32, UN/32), tb>>>(Wh0, wh0, UN, UN, UN);
    wconv<<<dim3(UN/32, UN/32), tb>>>(Wx1, wx1, UN, UN, UN);
    wconv<<<dim3(UN/32, UN/32), tb>>>(Wh1, wh1, UN, UN, UN);
    wconv<<<dim3(UN/32, KP/32),  tb>>>(Wx0, wx0, EMBD, UN, KP);

    cudaFuncSetAttribute(rnn_mma, cudaFuncAttributeMaxDynamicSharedMemorySize, SM_TOTAL);
    rnn_mma<<<NCTA, NTHR, SM_TOTAL>>>(b0, b1, Wo, bo, out);
}